// round 15
// baseline (speedup 1.0000x reference)
#include <cuda_runtime.h>

#define D_MODEL 1024
#define N_TOK   2048
#define HEADS   16
#define DH      64
#define NELEM   (D_MODEL * N_TOK)

// ---------------- scratch (device globals; no runtime allocation) ----------
__device__ __align__(16) float g_Q[NELEM];                 // [h][dH][N], 1/8 folded in
__device__ __align__(16) float g_K[NELEM];                 // [h][dH][N]
__device__ __align__(16) float g_V[NELEM];                 // [h][dH][N]
__device__ __align__(16) float g_attn[NELEM];              // [h*dH][N]
__device__ __align__(16) float g_S[67108864];              // [h][N][N] scores/probs (268 MB)
__device__ float g_psum[1024];
__device__ float g_psq[1024];
__device__ float g_stats[2];                               // [0]=mean, [1]=rstd

// ================= K1: per-block partial sums over x ========================
__global__ void reduce1_kernel(const float* __restrict__ x) {
    __shared__ float ss[256];
    __shared__ float sq[256];
    int tid  = threadIdx.x;
    int base = blockIdx.x * 2048 + tid;
    float s = 0.f, q = 0.f;
#pragma unroll
    for (int i = 0; i < 8; i++) {
        float v = x[base + i * 256];
        s += v; q += v * v;
    }
    ss[tid] = s; sq[tid] = q;
    __syncthreads();
    for (int o = 128; o > 0; o >>= 1) {
        if (tid < o) { ss[tid] += ss[tid + o]; sq[tid] += sq[tid + o]; }
        __syncthreads();
    }
    if (tid == 0) { g_psum[blockIdx.x] = ss[0]; g_psq[blockIdx.x] = sq[0]; }
}

// ================= K2: finalize mean / rstd =================================
__global__ void reduce2_kernel() {
    __shared__ float ss[256];
    __shared__ float sq[256];
    int tid = threadIdx.x;
    float s = 0.f, q = 0.f;
#pragma unroll
    for (int i = 0; i < 4; i++) { s += g_psum[tid + i * 256]; q += g_psq[tid + i * 256]; }
    ss[tid] = s; sq[tid] = q;
    __syncthreads();
    for (int o = 128; o > 0; o >>= 1) {
        if (tid < o) { ss[tid] += ss[tid + o]; sq[tid] += sq[tid + o]; }
        __syncthreads();
    }
    if (tid == 0) {
        float inv  = 1.f / (float)NELEM;
        float mean = ss[0] * inv;
        float var  = sq[0] * inv - mean * mean;
        g_stats[0] = mean;
        g_stats[1] = rsqrtf(var + 1e-5f);
    }
}

// ================= K3: fused LN + QKV projection ============================
// C[m][n] = sum_c W[h(m)][c][dh(m)] * xn[c][n];  m = h*64+dh, grid.z selects Q/K/V
__global__ void qkv_kernel(const float* __restrict__ x,
                           const float* __restrict__ WQ,
                           const float* __restrict__ WK,
                           const float* __restrict__ WV) {
    __shared__ __align__(16) float As[16][128];
    __shared__ __align__(16) float Bs[16][128];
    const float* W  = (blockIdx.z == 0) ? WQ  : (blockIdx.z == 1) ? WK  : WV;
    float*       out = (blockIdx.z == 0) ? g_Q : (blockIdx.z == 1) ? g_K : g_V;
    const float  sc  = (blockIdx.z == 0) ? 0.125f : 1.0f;   // 1/sqrt(dH) folded into Q
    const float  mean = g_stats[0], rstd = g_stats[1];

    int tid = threadIdx.x;
    int tx = tid & 15, ty = tid >> 4;
    int m0 = blockIdx.y * 128, n0 = blockIdx.x * 128;
    float acc[8][8] = {};

    for (int k0 = 0; k0 < D_MODEL; k0 += 16) {
        // A tile: W[(m>>6)<<16 + c*64 + (m&63)], coalesced along dh
#pragma unroll
        for (int r = 0; r < 8; r++) {
            int f = r * 256 + tid;
            int k = f >> 7, m = f & 127;
            int mg = m0 + m;
            As[k][m] = W[((mg >> 6) << 16) + (k0 + k) * 64 + (mg & 63)];
        }
        // B tile: LayerNorm applied on load
#pragma unroll
        for (int r = 0; r < 2; r++) {
            int f = r * 256 + tid;
            int k = f >> 5, n4 = f & 31;
            float4 v = *(const float4*)&x[(size_t)(k0 + k) * N_TOK + n0 + n4 * 4];
            v.x = (v.x - mean) * rstd; v.y = (v.y - mean) * rstd;
            v.z = (v.z - mean) * rstd; v.w = (v.w - mean) * rstd;
            *(float4*)&Bs[k][n4 * 4] = v;
        }
        __syncthreads();
#pragma unroll
        for (int k = 0; k < 16; k++) {
            float a[8], b[8];
            *(float4*)&a[0] = *(const float4*)&As[k][ty * 8];
            *(float4*)&a[4] = *(const float4*)&As[k][ty * 8 + 4];
            *(float4*)&b[0] = *(const float4*)&Bs[k][tx * 8];
            *(float4*)&b[4] = *(const float4*)&Bs[k][tx * 8 + 4];
#pragma unroll
            for (int i = 0; i < 8; i++)
#pragma unroll
                for (int j = 0; j < 8; j++)
                    acc[i][j] += a[i] * b[j];
        }
        __syncthreads();
    }
#pragma unroll
    for (int i = 0; i < 8; i++) {
        int m = m0 + ty * 8 + i;
#pragma unroll
        for (int j = 0; j < 8; j += 4) {
            float4 v = make_float4(acc[i][j] * sc, acc[i][j+1] * sc,
                                   acc[i][j+2] * sc, acc[i][j+3] * sc);
            *(float4*)&out[(size_t)m * N_TOK + n0 + tx * 8 + j] = v;
        }
    }
}

// ================= K4: S = (Q/8)^T K, per head ==============================
// S[i][j] = sum_d Q[d][i] K[d][j]; M=N=2048, K=64
__global__ void scores_kernel() {
    __shared__ __align__(16) float As[8][128];
    __shared__ __align__(16) float Bs[8][128];
    int h = blockIdx.z;
    const float* Q = g_Q + (size_t)h * DH * N_TOK;
    const float* K = g_K + (size_t)h * DH * N_TOK;
    float*       S = g_S + (size_t)h * N_TOK * N_TOK;

    int tid = threadIdx.x;
    int tx = tid & 15, ty = tid >> 4;
    int m0 = blockIdx.y * 128, n0 = blockIdx.x * 128;
    float acc[8][8] = {};

    for (int k0 = 0; k0 < DH; k0 += 8) {
        int kk = tid >> 5, g = tid & 31;
        *(float4*)&As[kk][g * 4] = *(const float4*)&Q[(size_t)(k0 + kk) * N_TOK + m0 + g * 4];
        *(float4*)&Bs[kk][g * 4] = *(const float4*)&K[(size_t)(k0 + kk) * N_TOK + n0 + g * 4];
        __syncthreads();
#pragma unroll
        for (int k = 0; k < 8; k++) {
            float a[8], b[8];
            *(float4*)&a[0] = *(const float4*)&As[k][ty * 8];
            *(float4*)&a[4] = *(const float4*)&As[k][ty * 8 + 4];
            *(float4*)&b[0] = *(const float4*)&Bs[k][tx * 8];
            *(float4*)&b[4] = *(const float4*)&Bs[k][tx * 8 + 4];
#pragma unroll
            for (int i = 0; i < 8; i++)
#pragma unroll
                for (int j = 0; j < 8; j++)
                    acc[i][j] += a[i] * b[j];
        }
        __syncthreads();
    }
#pragma unroll
    for (int i = 0; i < 8; i++) {
        size_t row = (size_t)(m0 + ty * 8 + i) * N_TOK + n0 + tx * 8;
#pragma unroll
        for (int j = 0; j < 8; j += 4)
            *(float4*)&S[row + j] = make_float4(acc[i][j], acc[i][j+1], acc[i][j+2], acc[i][j+3]);
    }
}

// ================= K5: row softmax in-place =================================
__global__ void softmax_kernel() {
    __shared__ float red[256];
    float* row = g_S + (size_t)blockIdx.x * N_TOK;
    int tid = threadIdx.x;
    float v[8];
    float mx = -1e30f;
#pragma unroll
    for (int i = 0; i < 8; i++) { v[i] = row[tid + i * 256]; mx = fmaxf(mx, v[i]); }
    red[tid] = mx;
    __syncthreads();
    for (int o = 128; o > 0; o >>= 1) {
        if (tid < o) red[tid] = fmaxf(red[tid], red[tid + o]);
        __syncthreads();
    }
    mx = red[0];
    __syncthreads();
    float s = 0.f;
#pragma unroll
    for (int i = 0; i < 8; i++) { v[i] = expf(v[i] - mx); s += v[i]; }
    red[tid] = s;
    __syncthreads();
    for (int o = 128; o > 0; o >>= 1) {
        if (tid < o) red[tid] += red[tid + o];
        __syncthreads();
    }
    float inv = 1.f / red[0];
#pragma unroll
    for (int i = 0; i < 8; i++) row[tid + i * 256] = v[i] * inv;
}

// ================= K6: attn = V @ P^T, per head =============================
// C[dh][i] = sum_j V[dh][j] * P[i][j]; M=64, N=2048, K=2048
__global__ void pv_kernel() {
    __shared__ float As[16][66];    // pad: 66 % 8 == 2 -> 4-row STS groups on disjoint bank octets
    __shared__ float Bs[16][130];   // 130 % 8 == 2
    int h = blockIdx.y;
    const float* V = g_V + (size_t)h * DH * N_TOK;
    const float* P = g_S + (size_t)h * N_TOK * N_TOK;

    int tid = threadIdx.x;
    int tx = tid & 15, ty = tid >> 4;   // tx -> 8 cols, ty -> 4 rows
    int n0 = blockIdx.x * 128;
    float acc[4][8] = {};

    for (int k0 = 0; k0 < N_TOK; k0 += 16) {
        {   // A tile: V [64][2048] row-major -> As[k][m]
            int kg = tid & 3, m = tid >> 2;
            float4 a = *(const float4*)&V[(size_t)m * N_TOK + k0 + kg * 4];
            As[kg*4+0][m] = a.x; As[kg*4+1][m] = a.y;
            As[kg*4+2][m] = a.z; As[kg*4+3][m] = a.w;
        }
        {   // B tile: P[n][k] -> Bs[k][n] (transpose on store)
            int kg = tid & 3, nn = tid >> 2;
#pragma unroll
            for (int r = 0; r < 2; r++) {
                int n = nn + r * 64;
                float4 b = *(const float4*)&P[(size_t)(n0 + n) * N_TOK + k0 + kg * 4];
                Bs[kg*4+0][n] = b.x; Bs[kg*4+1][n] = b.y;
                Bs[kg*4+2][n] = b.z; Bs[kg*4+3][n] = b.w;
            }
        }
        __syncthreads();
#pragma unroll
        for (int k = 0; k < 16; k++) {
            float a[4], b[8];
#pragma unroll
            for (int i = 0; i < 4; i++) a[i] = As[k][ty * 4 + i];
#pragma unroll
            for (int j = 0; j < 8; j++) b[j] = Bs[k][tx * 8 + j];
#pragma unroll
            for (int i = 0; i < 4; i++)
#pragma unroll
                for (int j = 0; j < 8; j++)
                    acc[i][j] += a[i] * b[j];
        }
        __syncthreads();
    }
#pragma unroll
    for (int i = 0; i < 4; i++) {
        size_t row = (size_t)(h * DH + ty * 4 + i) * N_TOK + n0 + tx * 8;
#pragma unroll
        for (int j = 0; j < 8; j += 4)
            *(float4*)&g_attn[row + j] = make_float4(acc[i][j], acc[i][j+1], acc[i][j+2], acc[i][j+3]);
    }
}

// ================= K7: out = W0 @ attn + x ==================================
__global__ void out_kernel(const float* __restrict__ x,
                           const float* __restrict__ W0,
                           float* __restrict__ out) {
    __shared__ float As[16][130];
    __shared__ __align__(16) float Bs[16][128];
    int tid = threadIdx.x;
    int tx = tid & 15, ty = tid >> 4;
    int m0 = blockIdx.y * 128, n0 = blockIdx.x * 128;
    float acc[8][8] = {};

    for (int k0 = 0; k0 < D_MODEL; k0 += 16) {
        {   // A tile: W0 [1024][1024] row-major -> As[k][m] (transpose on store)
            int kg = tid & 3, mm = tid >> 2;
#pragma unroll
            for (int r = 0; r < 2; r++) {
                int m = mm + r * 64;
                float4 a = *(const float4*)&W0[(size_t)(m0 + m) * D_MODEL + k0 + kg * 4];
                As[kg*4+0][m] = a.x; As[kg*4+1][m] = a.y;
                As[kg*4+2][m] = a.z; As[kg*4+3][m] = a.w;
            }
        }
#pragma unroll
        for (int r = 0; r < 2; r++) {
            int f = r * 256 + tid;
            int k = f >> 5, n4 = f & 31;
            *(float4*)&Bs[k][n4 * 4] =
                *(const float4*)&g_attn[(size_t)(k0 + k) * N_TOK + n0 + n4 * 4];
        }
        __syncthreads();
#pragma unroll
        for (int k = 0; k < 16; k++) {
            float a[8], b[8];
#pragma unroll
            for (int i = 0; i < 8; i++) a[i] = As[k][ty * 8 + i];
            *(float4*)&b[0] = *(const float4*)&Bs[k][tx * 8];
            *(float4*)&b[4] = *(const float4*)&Bs[k][tx * 8 + 4];
#pragma unroll
            for (int i = 0; i < 8; i++)
#pragma unroll
                for (int j = 0; j < 8; j++)
                    acc[i][j] += a[i] * b[j];
        }
        __syncthreads();
    }
#pragma unroll
    for (int i = 0; i < 8; i++) {
        int m = m0 + ty * 8 + i;
        size_t row = (size_t)m * N_TOK + n0 + tx * 8;
#pragma unroll
        for (int j = 0; j < 8; j += 4) {
            float4 r = *(const float4*)&x[row + j];   // residual
            r.x += acc[i][j]; r.y += acc[i][j+1]; r.z += acc[i][j+2]; r.w += acc[i][j+3];
            *(float4*)&out[row + j] = r;
        }
    }
}

// ================= launch ====================================================
extern "C" void kernel_launch(void* const* d_in, const int* in_sizes, int n_in,
                              void* d_out, int out_size) {
    (void)in_sizes; (void)n_in; (void)out_size;
    const float* x  = (const float*)d_in[0];
    const float* WQ = (const float*)d_in[1];
    const float* WK = (const float*)d_in[2];
    const float* WV = (const float*)d_in[3];
    const float* W0 = (const float*)d_in[4];
    float* out = (float*)d_out;

    reduce1_kernel<<<1024, 256>>>(x);
    reduce2_kernel<<<1, 256>>>();
    qkv_kernel<<<dim3(16, 8, 3), 256>>>(x, WQ, WK, WV);
    scores_kernel<<<dim3(16, 16, 16), 256>>>();
    softmax_kernel<<<HEADS * N_TOK, 256>>>();
    pv_kernel<<<dim3(16, 16), 256>>>();
    out_kernel<<<dim3(16, 8), 256>>>(x, W0, out);
}

// round 16
// speedup vs baseline: 1.0002x; 1.0002x over previous
#include <cuda_runtime.h>

#define D_MODEL 1024
#define N_TOK   2048
#define HEADS   16
#define DH      64
#define NELEM   (D_MODEL * N_TOK)

// ---------------- scratch (device globals; no runtime allocation) ----------
__device__ __align__(16) float g_Q[NELEM];                 // [h][dH][N], 1/8 folded in
__device__ __align__(16) float g_K[NELEM];                 // [h][dH][N]
__device__ __align__(16) float g_V[NELEM];                 // [h][dH][N]
__device__ __align__(16) float g_attn[NELEM];              // [h*dH][N]
__device__ __align__(16) float g_S[67108864];              // [h][N][N] scores/probs (268 MB)
__device__ float g_psum[1024];
__device__ float g_psq[1024];
__device__ float g_stats[2];                               // [0]=mean, [1]=rstd

// ================= K1: per-block partial sums over x ========================
__global__ void reduce1_kernel(const float* __restrict__ x) {
    __shared__ float ss[256];
    __shared__ float sq[256];
    int tid  = threadIdx.x;
    int base = blockIdx.x * 2048 + tid;
    float s = 0.f, q = 0.f;
#pragma unroll
    for (int i = 0; i < 8; i++) {
        float v = x[base + i * 256];
        s += v; q += v * v;
    }
    ss[tid] = s; sq[tid] = q;
    __syncthreads();
    for (int o = 128; o > 0; o >>= 1) {
        if (tid < o) { ss[tid] += ss[tid + o]; sq[tid] += sq[tid + o]; }
        __syncthreads();
    }
    if (tid == 0) { g_psum[blockIdx.x] = ss[0]; g_psq[blockIdx.x] = sq[0]; }
}

// ================= K2: finalize mean / rstd =================================
__global__ void reduce2_kernel() {
    __shared__ float ss[256];
    __shared__ float sq[256];
    int tid = threadIdx.x;
    float s = 0.f, q = 0.f;
#pragma unroll
    for (int i = 0; i < 4; i++) { s += g_psum[tid + i * 256]; q += g_psq[tid + i * 256]; }
    ss[tid] = s; sq[tid] = q;
    __syncthreads();
    for (int o = 128; o > 0; o >>= 1) {
        if (tid < o) { ss[tid] += ss[tid + o]; sq[tid] += sq[tid + o]; }
        __syncthreads();
    }
    if (tid == 0) {
        float inv  = 1.f / (float)NELEM;
        float mean = ss[0] * inv;
        float var  = sq[0] * inv - mean * mean;
        g_stats[0] = mean;
        g_stats[1] = rsqrtf(var + 1e-5f);
    }
}

// ================= K3: fused LN + QKV projection ============================
// C[m][n] = sum_c W[h(m)][c][dh(m)] * xn[c][n];  m = h*64+dh, grid.z selects Q/K/V
__global__ void qkv_kernel(const float* __restrict__ x,
                           const float* __restrict__ WQ,
                           const float* __restrict__ WK,
                           const float* __restrict__ WV) {
    __shared__ __align__(16) float As[16][128];
    __shared__ __align__(16) float Bs[16][128];
    const float* W  = (blockIdx.z == 0) ? WQ  : (blockIdx.z == 1) ? WK  : WV;
    float*       out = (blockIdx.z == 0) ? g_Q : (blockIdx.z == 1) ? g_K : g_V;
    const float  sc  = (blockIdx.z == 0) ? 0.125f : 1.0f;   // 1/sqrt(dH) folded into Q
    const float  mean = g_stats[0], rstd = g_stats[1];

    int tid = threadIdx.x;
    int tx = tid & 15, ty = tid >> 4;
    int m0 = blockIdx.y * 128, n0 = blockIdx.x * 128;
    float acc[8][8] = {};

    for (int k0 = 0; k0 < D_MODEL; k0 += 16) {
        // A tile: W[(m>>6)<<16 + c*64 + (m&63)], coalesced along dh
#pragma unroll
        for (int r = 0; r < 8; r++) {
            int f = r * 256 + tid;
            int k = f >> 7, m = f & 127;
            int mg = m0 + m;
            As[k][m] = W[((mg >> 6) << 16) + (k0 + k) * 64 + (mg & 63)];
        }
        // B tile: LayerNorm applied on load
#pragma unroll
        for (int r = 0; r < 2; r++) {
            int f = r * 256 + tid;
            int k = f >> 5, n4 = f & 31;
            float4 v = *(const float4*)&x[(size_t)(k0 + k) * N_TOK + n0 + n4 * 4];
            v.x = (v.x - mean) * rstd; v.y = (v.y - mean) * rstd;
            v.z = (v.z - mean) * rstd; v.w = (v.w - mean) * rstd;
            *(float4*)&Bs[k][n4 * 4] = v;
        }
        __syncthreads();
#pragma unroll
        for (int k = 0; k < 16; k++) {
            float a[8], b[8];
            *(float4*)&a[0] = *(const float4*)&As[k][ty * 8];
            *(float4*)&a[4] = *(const float4*)&As[k][ty * 8 + 4];
            *(float4*)&b[0] = *(const float4*)&Bs[k][tx * 8];
            *(float4*)&b[4] = *(const float4*)&Bs[k][tx * 8 + 4];
#pragma unroll
            for (int i = 0; i < 8; i++)
#pragma unroll
                for (int j = 0; j < 8; j++)
                    acc[i][j] += a[i] * b[j];
        }
        __syncthreads();
    }
#pragma unroll
    for (int i = 0; i < 8; i++) {
        int m = m0 + ty * 8 + i;
#pragma unroll
        for (int j = 0; j < 8; j += 4) {
            float4 v = make_float4(acc[i][j] * sc, acc[i][j+1] * sc,
                                   acc[i][j+2] * sc, acc[i][j+3] * sc);
            *(float4*)&out[(size_t)m * N_TOK + n0 + tx * 8 + j] = v;
        }
    }
}

// ================= K4: S = (Q/8)^T K, per head ==============================
// S[i][j] = sum_d Q[d][i] K[d][j]; M=N=2048, K=64
__global__ void scores_kernel() {
    __shared__ __align__(16) float As[8][128];
    __shared__ __align__(16) float Bs[8][128];
    int h = blockIdx.z;
    const float* Q = g_Q + (size_t)h * DH * N_TOK;
    const float* K = g_K + (size_t)h * DH * N_TOK;
    float*       S = g_S + (size_t)h * N_TOK * N_TOK;

    int tid = threadIdx.x;
    int tx = tid & 15, ty = tid >> 4;
    int m0 = blockIdx.y * 128, n0 = blockIdx.x * 128;
    float acc[8][8] = {};

    for (int k0 = 0; k0 < DH; k0 += 8) {
        int kk = tid >> 5, g = tid & 31;
        *(float4*)&As[kk][g * 4] = *(const float4*)&Q[(size_t)(k0 + kk) * N_TOK + m0 + g * 4];
        *(float4*)&Bs[kk][g * 4] = *(const float4*)&K[(size_t)(k0 + kk) * N_TOK + n0 + g * 4];
        __syncthreads();
#pragma unroll
        for (int k = 0; k < 8; k++) {
            float a[8], b[8];
            *(float4*)&a[0] = *(const float4*)&As[k][ty * 8];
            *(float4*)&a[4] = *(const float4*)&As[k][ty * 8 + 4];
            *(float4*)&b[0] = *(const float4*)&Bs[k][tx * 8];
            *(float4*)&b[4] = *(const float4*)&Bs[k][tx * 8 + 4];
#pragma unroll
            for (int i = 0; i < 8; i++)
#pragma unroll
                for (int j = 0; j < 8; j++)
                    acc[i][j] += a[i] * b[j];
        }
        __syncthreads();
    }
#pragma unroll
    for (int i = 0; i < 8; i++) {
        size_t row = (size_t)(m0 + ty * 8 + i) * N_TOK + n0 + tx * 8;
#pragma unroll
        for (int j = 0; j < 8; j += 4)
            *(float4*)&S[row + j] = make_float4(acc[i][j], acc[i][j+1], acc[i][j+2], acc[i][j+3]);
    }
}

// ================= K5: row softmax in-place =================================
__global__ void softmax_kernel() {
    __shared__ float red[256];
    float* row = g_S + (size_t)blockIdx.x * N_TOK;
    int tid = threadIdx.x;
    float v[8];
    float mx = -1e30f;
#pragma unroll
    for (int i = 0; i < 8; i++) { v[i] = row[tid + i * 256]; mx = fmaxf(mx, v[i]); }
    red[tid] = mx;
    __syncthreads();
    for (int o = 128; o > 0; o >>= 1) {
        if (tid < o) red[tid] = fmaxf(red[tid], red[tid + o]);
        __syncthreads();
    }
    mx = red[0];
    __syncthreads();
    float s = 0.f;
#pragma unroll
    for (int i = 0; i < 8; i++) { v[i] = expf(v[i] - mx); s += v[i]; }
    red[tid] = s;
    __syncthreads();
    for (int o = 128; o > 0; o >>= 1) {
        if (tid < o) red[tid] += red[tid + o];
        __syncthreads();
    }
    float inv = 1.f / red[0];
#pragma unroll
    for (int i = 0; i < 8; i++) row[tid + i * 256] = v[i] * inv;
}

// ================= K6: attn = V @ P^T, per head =============================
// C[dh][i] = sum_j V[dh][j] * P[i][j]; M=64, N=2048, K=2048
__global__ void pv_kernel() {
    __shared__ float As[16][66];    // pad: 66 % 8 == 2 -> 4-row STS groups on disjoint bank octets
    __shared__ float Bs[16][130];   // 130 % 8 == 2
    int h = blockIdx.y;
    const float* V = g_V + (size_t)h * DH * N_TOK;
    const float* P = g_S + (size_t)h * N_TOK * N_TOK;

    int tid = threadIdx.x;
    int tx = tid & 15, ty = tid >> 4;   // tx -> 8 cols, ty -> 4 rows
    int n0 = blockIdx.x * 128;
    float acc[4][8] = {};

    for (int k0 = 0; k0 < N_TOK; k0 += 16) {
        {   // A tile: V [64][2048] row-major -> As[k][m]
            int kg = tid & 3, m = tid >> 2;
            float4 a = *(const float4*)&V[(size_t)m * N_TOK + k0 + kg * 4];
            As[kg*4+0][m] = a.x; As[kg*4+1][m] = a.y;
            As[kg*4+2][m] = a.z; As[kg*4+3][m] = a.w;
        }
        {   // B tile: P[n][k] -> Bs[k][n] (transpose on store)
            int kg = tid & 3, nn = tid >> 2;
#pragma unroll
            for (int r = 0; r < 2; r++) {
                int n = nn + r * 64;
                float4 b = *(const float4*)&P[(size_t)(n0 + n) * N_TOK + k0 + kg * 4];
                Bs[kg*4+0][n] = b.x; Bs[kg*4+1][n] = b.y;
                Bs[kg*4+2][n] = b.z; Bs[kg*4+3][n] = b.w;
            }
        }
        __syncthreads();
#pragma unroll
        for (int k = 0; k < 16; k++) {
            float a[4], b[8];
#pragma unroll
            for (int i = 0; i < 4; i++) a[i] = As[k][ty * 4 + i];
#pragma unroll
            for (int j = 0; j < 8; j++) b[j] = Bs[k][tx * 8 + j];
#pragma unroll
            for (int i = 0; i < 4; i++)
#pragma unroll
                for (int j = 0; j < 8; j++)
                    acc[i][j] += a[i] * b[j];
        }
        __syncthreads();
    }
#pragma unroll
    for (int i = 0; i < 4; i++) {
        size_t row = (size_t)(h * DH + ty * 4 + i) * N_TOK + n0 + tx * 8;
#pragma unroll
        for (int j = 0; j < 8; j += 4)
            *(float4*)&g_attn[row + j] = make_float4(acc[i][j], acc[i][j+1], acc[i][j+2], acc[i][j+3]);
    }
}

// ================= K7: out = W0 @ attn + x ==================================
__global__ void out_kernel(const float* __restrict__ x,
                           const float* __restrict__ W0,
                           float* __restrict__ out) {
    __shared__ float As[16][130];
    __shared__ __align__(16) float Bs[16][128];
    int tid = threadIdx.x;
    int tx = tid & 15, ty = tid >> 4;
    int m0 = blockIdx.y * 128, n0 = blockIdx.x * 128;
    float acc[8][8] = {};

    for (int k0 = 0; k0 < D_MODEL; k0 += 16) {
        {   // A tile: W0 [1024][1024] row-major -> As[k][m] (transpose on store)
            int kg = tid & 3, mm = tid >> 2;
#pragma unroll
            for (int r = 0; r < 2; r++) {
                int m = mm + r * 64;
                float4 a = *(const float4*)&W0[(size_t)(m0 + m) * D_MODEL + k0 + kg * 4];
                As[kg*4+0][m] = a.x; As[kg*4+1][m] = a.y;
                As[kg*4+2][m] = a.z; As[kg*4+3][m] = a.w;
            }
        }
#pragma unroll
        for (int r = 0; r < 2; r++) {
            int f = r * 256 + tid;
            int k = f >> 5, n4 = f & 31;
            *(float4*)&Bs[k][n4 * 4] =
                *(const float4*)&g_attn[(size_t)(k0 + k) * N_TOK + n0 + n4 * 4];
        }
        __syncthreads();
#pragma unroll
        for (int k = 0; k < 16; k++) {
            float a[8], b[8];
#pragma unroll
            for (int i = 0; i < 8; i++) a[i] = As[k][ty * 8 + i];
            *(float4*)&b[0] = *(const float4*)&Bs[k][tx * 8];
            *(float4*)&b[4] = *(const float4*)&Bs[k][tx * 8 + 4];
#pragma unroll
            for (int i = 0; i < 8; i++)
#pragma unroll
                for (int j = 0; j < 8; j++)
                    acc[i][j] += a[i] * b[j];
        }
        __syncthreads();
    }
#pragma unroll
    for (int i = 0; i < 8; i++) {
        int m = m0 + ty * 8 + i;
        size_t row = (size_t)m * N_TOK + n0 + tx * 8;
#pragma unroll
        for (int j = 0; j < 8; j += 4) {
            float4 r = *(const float4*)&x[row + j];   // residual
            r.x += acc[i][j]; r.y += acc[i][j+1]; r.z += acc[i][j+2]; r.w += acc[i][j+3];
            *(float4*)&out[row + j] = r;
        }
    }
}

// ================= launch ====================================================
extern "C" void kernel_launch(void* const* d_in, const int* in_sizes, int n_in,
                              void* d_out, int out_size) {
    (void)in_sizes; (void)n_in; (void)out_size;
    const float* x  = (const float*)d_in[0];
    const float* WQ = (const float*)d_in[1];
    const float* WK = (const float*)d_in[2];
    const float* WV = (const float*)d_in[3];
    const float* W0 = (const float*)d_in[4];
    float* out = (float*)d_out;

    reduce1_kernel<<<1024, 256>>>(x);
    reduce2_kernel<<<1, 256>>>();
    qkv_kernel<<<dim3(16, 8, 3), 256>>>(x, WQ, WK, WV);
    scores_kernel<<<dim3(16, 16, 16), 256>>>();
    softmax_kernel<<<HEADS * N_TOK, 256>>>();
    pv_kernel<<<dim3(16, 16), 256>>>();
    out_kernel<<<dim3(16, 8), 256>>>(x, W0, out);
}

// round 17
// speedup vs baseline: 1.0032x; 1.0030x over previous
#include <cuda_runtime.h>

#define D_MODEL 1024
#define N_TOK   2048
#define HEADS   16
#define DH      64
#define NELEM   (D_MODEL * N_TOK)

// ---------------- scratch (device globals; no runtime allocation) ----------
__device__ __align__(16) float g_Q[NELEM];                 // [h][dH][N], 1/8 folded in
__device__ __align__(16) float g_K[NELEM];                 // [h][dH][N]
__device__ __align__(16) float g_V[NELEM];                 // [h][dH][N]
__device__ __align__(16) float g_attn[NELEM];              // [h*dH][N]
__device__ __align__(16) float g_S[67108864];              // [h][N][N] scores/probs (268 MB)
__device__ float g_psum[1024];
__device__ float g_psq[1024];
__device__ float g_stats[2];                               // [0]=mean, [1]=rstd

// ================= K1: per-block partial sums over x ========================
__global__ void reduce1_kernel(const float* __restrict__ x) {
    __shared__ float ss[256];
    __shared__ float sq[256];
    int tid  = threadIdx.x;
    int base = blockIdx.x * 2048 + tid;
    float s = 0.f, q = 0.f;
#pragma unroll
    for (int i = 0; i < 8; i++) {
        float v = x[base + i * 256];
        s += v; q += v * v;
    }
    ss[tid] = s; sq[tid] = q;
    __syncthreads();
    for (int o = 128; o > 0; o >>= 1) {
        if (tid < o) { ss[tid] += ss[tid + o]; sq[tid] += sq[tid + o]; }
        __syncthreads();
    }
    if (tid == 0) { g_psum[blockIdx.x] = ss[0]; g_psq[blockIdx.x] = sq[0]; }
}

// ================= K2: finalize mean / rstd =================================
__global__ void reduce2_kernel() {
    __shared__ float ss[256];
    __shared__ float sq[256];
    int tid = threadIdx.x;
    float s = 0.f, q = 0.f;
#pragma unroll
    for (int i = 0; i < 4; i++) { s += g_psum[tid + i * 256]; q += g_psq[tid + i * 256]; }
    ss[tid] = s; sq[tid] = q;
    __syncthreads();
    for (int o = 128; o > 0; o >>= 1) {
        if (tid < o) { ss[tid] += ss[tid + o]; sq[tid] += sq[tid + o]; }
        __syncthreads();
    }
    if (tid == 0) {
        float inv  = 1.f / (float)NELEM;
        float mean = ss[0] * inv;
        float var  = sq[0] * inv - mean * mean;
        g_stats[0] = mean;
        g_stats[1] = rsqrtf(var + 1e-5f);
    }
}

// ================= K3: fused LN + QKV projection ============================
// C[m][n] = sum_c W[h(m)][c][dh(m)] * xn[c][n];  m = h*64+dh, grid.z selects Q/K/V
__global__ void qkv_kernel(const float* __restrict__ x,
                           const float* __restrict__ WQ,
                           const float* __restrict__ WK,
                           const float* __restrict__ WV) {
    __shared__ __align__(16) float As[16][128];
    __shared__ __align__(16) float Bs[16][128];
    const float* W  = (blockIdx.z == 0) ? WQ  : (blockIdx.z == 1) ? WK  : WV;
    float*       out = (blockIdx.z == 0) ? g_Q : (blockIdx.z == 1) ? g_K : g_V;
    const float  sc  = (blockIdx.z == 0) ? 0.125f : 1.0f;   // 1/sqrt(dH) folded into Q
    const float  mean = g_stats[0], rstd = g_stats[1];

    int tid = threadIdx.x;
    int tx = tid & 15, ty = tid >> 4;
    int m0 = blockIdx.y * 128, n0 = blockIdx.x * 128;
    float acc[8][8] = {};

    for (int k0 = 0; k0 < D_MODEL; k0 += 16) {
        // A tile: W[(m>>6)<<16 + c*64 + (m&63)], coalesced along dh
#pragma unroll
        for (int r = 0; r < 8; r++) {
            int f = r * 256 + tid;
            int k = f >> 7, m = f & 127;
            int mg = m0 + m;
            As[k][m] = W[((mg >> 6) << 16) + (k0 + k) * 64 + (mg & 63)];
        }
        // B tile: LayerNorm applied on load
#pragma unroll
        for (int r = 0; r < 2; r++) {
            int f = r * 256 + tid;
            int k = f >> 5, n4 = f & 31;
            float4 v = *(const float4*)&x[(size_t)(k0 + k) * N_TOK + n0 + n4 * 4];
            v.x = (v.x - mean) * rstd; v.y = (v.y - mean) * rstd;
            v.z = (v.z - mean) * rstd; v.w = (v.w - mean) * rstd;
            *(float4*)&Bs[k][n4 * 4] = v;
        }
        __syncthreads();
#pragma unroll
        for (int k = 0; k < 16; k++) {
            float a[8], b[8];
            *(float4*)&a[0] = *(const float4*)&As[k][ty * 8];
            *(float4*)&a[4] = *(const float4*)&As[k][ty * 8 + 4];
            *(float4*)&b[0] = *(const float4*)&Bs[k][tx * 8];
            *(float4*)&b[4] = *(const float4*)&Bs[k][tx * 8 + 4];
#pragma unroll
            for (int i = 0; i < 8; i++)
#pragma unroll
                for (int j = 0; j < 8; j++)
                    acc[i][j] += a[i] * b[j];
        }
        __syncthreads();
    }
#pragma unroll
    for (int i = 0; i < 8; i++) {
        int m = m0 + ty * 8 + i;
#pragma unroll
        for (int j = 0; j < 8; j += 4) {
            float4 v = make_float4(acc[i][j] * sc, acc[i][j+1] * sc,
                                   acc[i][j+2] * sc, acc[i][j+3] * sc);
            *(float4*)&out[(size_t)m * N_TOK + n0 + tx * 8 + j] = v;
        }
    }
}

// ================= K4: S = (Q/8)^T K, per head ==============================
// S[i][j] = sum_d Q[d][i] K[d][j]; M=N=2048, K=64
__global__ void scores_kernel() {
    __shared__ __align__(16) float As[8][128];
    __shared__ __align__(16) float Bs[8][128];
    int h = blockIdx.z;
    const float* Q = g_Q + (size_t)h * DH * N_TOK;
    const float* K = g_K + (size_t)h * DH * N_TOK;
    float*       S = g_S + (size_t)h * N_TOK * N_TOK;

    int tid = threadIdx.x;
    int tx = tid & 15, ty = tid >> 4;
    int m0 = blockIdx.y * 128, n0 = blockIdx.x * 128;
    float acc[8][8] = {};

    for (int k0 = 0; k0 < DH; k0 += 8) {
        int kk = tid >> 5, g = tid & 31;
        *(float4*)&As[kk][g * 4] = *(const float4*)&Q[(size_t)(k0 + kk) * N_TOK + m0 + g * 4];
        *(float4*)&Bs[kk][g * 4] = *(const float4*)&K[(size_t)(k0 + kk) * N_TOK + n0 + g * 4];
        __syncthreads();
#pragma unroll
        for (int k = 0; k < 8; k++) {
            float a[8], b[8];
            *(float4*)&a[0] = *(const float4*)&As[k][ty * 8];
            *(float4*)&a[4] = *(const float4*)&As[k][ty * 8 + 4];
            *(float4*)&b[0] = *(const float4*)&Bs[k][tx * 8];
            *(float4*)&b[4] = *(const float4*)&Bs[k][tx * 8 + 4];
#pragma unroll
            for (int i = 0; i < 8; i++)
#pragma unroll
                for (int j = 0; j < 8; j++)
                    acc[i][j] += a[i] * b[j];
        }
        __syncthreads();
    }
#pragma unroll
    for (int i = 0; i < 8; i++) {
        size_t row = (size_t)(m0 + ty * 8 + i) * N_TOK + n0 + tx * 8;
#pragma unroll
        for (int j = 0; j < 8; j += 4)
            *(float4*)&S[row + j] = make_float4(acc[i][j], acc[i][j+1], acc[i][j+2], acc[i][j+3]);
    }
}

// ================= K5: row softmax in-place =================================
__global__ void softmax_kernel() {
    __shared__ float red[256];
    float* row = g_S + (size_t)blockIdx.x * N_TOK;
    int tid = threadIdx.x;
    float v[8];
    float mx = -1e30f;
#pragma unroll
    for (int i = 0; i < 8; i++) { v[i] = row[tid + i * 256]; mx = fmaxf(mx, v[i]); }
    red[tid] = mx;
    __syncthreads();
    for (int o = 128; o > 0; o >>= 1) {
        if (tid < o) red[tid] = fmaxf(red[tid], red[tid + o]);
        __syncthreads();
    }
    mx = red[0];
    __syncthreads();
    float s = 0.f;
#pragma unroll
    for (int i = 0; i < 8; i++) { v[i] = expf(v[i] - mx); s += v[i]; }
    red[tid] = s;
    __syncthreads();
    for (int o = 128; o > 0; o >>= 1) {
        if (tid < o) red[tid] += red[tid + o];
        __syncthreads();
    }
    float inv = 1.f / red[0];
#pragma unroll
    for (int i = 0; i < 8; i++) row[tid + i * 256] = v[i] * inv;
}

// ================= K6: attn = V @ P^T, per head =============================
// C[dh][i] = sum_j V[dh][j] * P[i][j]; M=64, N=2048, K=2048
__global__ void pv_kernel() {
    __shared__ float As[16][66];    // pad: 66 % 8 == 2 -> 4-row STS groups on disjoint bank octets
    __shared__ float Bs[16][130];   // 130 % 8 == 2
    int h = blockIdx.y;
    const float* V = g_V + (size_t)h * DH * N_TOK;
    const float* P = g_S + (size_t)h * N_TOK * N_TOK;

    int tid = threadIdx.x;
    int tx = tid & 15, ty = tid >> 4;   // tx -> 8 cols, ty -> 4 rows
    int n0 = blockIdx.x * 128;
    float acc[4][8] = {};

    for (int k0 = 0; k0 < N_TOK; k0 += 16) {
        {   // A tile: V [64][2048] row-major -> As[k][m]
            int kg = tid & 3, m = tid >> 2;
            float4 a = *(const float4*)&V[(size_t)m * N_TOK + k0 + kg * 4];
            As[kg*4+0][m] = a.x; As[kg*4+1][m] = a.y;
            As[kg*4+2][m] = a.z; As[kg*4+3][m] = a.w;
        }
        {   // B tile: P[n][k] -> Bs[k][n] (transpose on store)
            int kg = tid & 3, nn = tid >> 2;
#pragma unroll
            for (int r = 0; r < 2; r++) {
                int n = nn + r * 64;
                float4 b = *(const float4*)&P[(size_t)(n0 + n) * N_TOK + k0 + kg * 4];
                Bs[kg*4+0][n] = b.x; Bs[kg*4+1][n] = b.y;
                Bs[kg*4+2][n] = b.z; Bs[kg*4+3][n] = b.w;
            }
        }
        __syncthreads();
#pragma unroll
        for (int k = 0; k < 16; k++) {
            float a[4], b[8];
#pragma unroll
            for (int i = 0; i < 4; i++) a[i] = As[k][ty * 4 + i];
#pragma unroll
            for (int j = 0; j < 8; j++) b[j] = Bs[k][tx * 8 + j];
#pragma unroll
            for (int i = 0; i < 4; i++)
#pragma unroll
                for (int j = 0; j < 8; j++)
                    acc[i][j] += a[i] * b[j];
        }
        __syncthreads();
    }
#pragma unroll
    for (int i = 0; i < 4; i++) {
        size_t row = (size_t)(h * DH + ty * 4 + i) * N_TOK + n0 + tx * 8;
#pragma unroll
        for (int j = 0; j < 8; j += 4)
            *(float4*)&g_attn[row + j] = make_float4(acc[i][j], acc[i][j+1], acc[i][j+2], acc[i][j+3]);
    }
}

// ================= K7: out = W0 @ attn + x ==================================
__global__ void out_kernel(const float* __restrict__ x,
                           const float* __restrict__ W0,
                           float* __restrict__ out) {
    __shared__ float As[16][130];
    __shared__ __align__(16) float Bs[16][128];
    int tid = threadIdx.x;
    int tx = tid & 15, ty = tid >> 4;
    int m0 = blockIdx.y * 128, n0 = blockIdx.x * 128;
    float acc[8][8] = {};

    for (int k0 = 0; k0 < D_MODEL; k0 += 16) {
        {   // A tile: W0 [1024][1024] row-major -> As[k][m] (transpose on store)
            int kg = tid & 3, mm = tid >> 2;
#pragma unroll
            for (int r = 0; r < 2; r++) {
                int m = mm + r * 64;
                float4 a = *(const float4*)&W0[(size_t)(m0 + m) * D_MODEL + k0 + kg * 4];
                As[kg*4+0][m] = a.x; As[kg*4+1][m] = a.y;
                As[kg*4+2][m] = a.z; As[kg*4+3][m] = a.w;
            }
        }
#pragma unroll
        for (int r = 0; r < 2; r++) {
            int f = r * 256 + tid;
            int k = f >> 5, n4 = f & 31;
            *(float4*)&Bs[k][n4 * 4] =
                *(const float4*)&g_attn[(size_t)(k0 + k) * N_TOK + n0 + n4 * 4];
        }
        __syncthreads();
#pragma unroll
        for (int k = 0; k < 16; k++) {
            float a[8], b[8];
#pragma unroll
            for (int i = 0; i < 8; i++) a[i] = As[k][ty * 8 + i];
            *(float4*)&b[0] = *(const float4*)&Bs[k][tx * 8];
            *(float4*)&b[4] = *(const float4*)&Bs[k][tx * 8 + 4];
#pragma unroll
            for (int i = 0; i < 8; i++)
#pragma unroll
                for (int j = 0; j < 8; j++)
                    acc[i][j] += a[i] * b[j];
        }
        __syncthreads();
    }
#pragma unroll
    for (int i = 0; i < 8; i++) {
        int m = m0 + ty * 8 + i;
        size_t row = (size_t)m * N_TOK + n0 + tx * 8;
#pragma unroll
        for (int j = 0; j < 8; j += 4) {
            float4 r = *(const float4*)&x[row + j];   // residual
            r.x += acc[i][j]; r.y += acc[i][j+1]; r.z += acc[i][j+2]; r.w += acc[i][j+3];
            *(float4*)&out[row + j] = r;
        }
    }
}

// ================= launch ====================================================
extern "C" void kernel_launch(void* const* d_in, const int* in_sizes, int n_in,
                              void* d_out, int out_size) {
    (void)in_sizes; (void)n_in; (void)out_size;
    const float* x  = (const float*)d_in[0];
    const float* WQ = (const float*)d_in[1];
    const float* WK = (const float*)d_in[2];
    const float* WV = (const float*)d_in[3];
    const float* W0 = (const float*)d_in[4];
    float* out = (float*)d_out;

    reduce1_kernel<<<1024, 256>>>(x);
    reduce2_kernel<<<1, 256>>>();
    qkv_kernel<<<dim3(16, 8, 3), 256>>>(x, WQ, WK, WV);
    scores_kernel<<<dim3(16, 16, 16), 256>>>();
    softmax_kernel<<<HEADS * N_TOK, 256>>>();
    pv_kernel<<<dim3(16, 16), 256>>>();
    out_kernel<<<dim3(16, 8), 256>>>(x, W0, out);
}